// round 2
// baseline (speedup 1.0000x reference)
#include <cuda_runtime.h>
#include <math.h>

#define BB   8
#define NN   1024
#define KK   32
#define DD   256
#define NH   8
#define DHD  32
#define TD   16
#define NBF  32
#define HID_ 128
#define NS_  128
#define SHD_ 9
#define EIN_ 304
#define NL   4

// ---- scratch (device globals; no allocation allowed) ----
__device__ int   g_src [BB*NN*KK];
__device__ float g_cut [BB*NN*KK];
__device__ float g_sh  [BB*NN*KK*SHD_];
__device__ float g_rbf [BB*NN*KK*NBF];
__device__ float g_node[BB*NN*DD];
__device__ float g_q   [BB*NN*DD];
__device__ float g_agg [BB*NN*DD];

__device__ __forceinline__ float gelu_t(float x){
    // jax.nn.gelu default (approximate=True, tanh form)
    float x3 = x*x*x;
    return 0.5f*x*(1.0f + tanhf(0.7978845608028654f*(x + 0.044715f*x3)));
}

// ---------------- kNN: one warp per node, select 32 smallest (d2,idx) ----------------
__global__ void knn_kernel(const float* __restrict__ x){
    __shared__ unsigned long long keys[NN];
    int b = blockIdx.y, i = blockIdx.x, lane = threadIdx.x;
    const float* pos = x + b*NN*3;
    float xi = pos[3*i], yi = pos[3*i+1], zi = pos[3*i+2];
    for (int j = lane; j < NN; j += 32){
        float dx = xi - pos[3*j], dy = yi - pos[3*j+1], dz = zi - pos[3*j+2];
        float d2 = dx*dx + dy*dy + dz*dz;
        keys[j] = (((unsigned long long)__float_as_uint(d2)) << 32) | (unsigned int)j;
    }
    __syncwarp();
    int base = (b*NN + i)*KK;
    for (int k = 0; k < KK; k++){
        unsigned long long m = 0xFFFFFFFFFFFFFFFFULL; int mp = -1;
        for (int j = lane; j < NN; j += 32)
            if (keys[j] < m){ m = keys[j]; mp = j; }
        unsigned long long gm = m;
        #pragma unroll
        for (int off = 16; off; off >>= 1){
            unsigned long long o = __shfl_xor_sync(0xFFFFFFFFu, gm, off);
            if (o < gm) gm = o;
        }
        if (m == gm && mp >= 0) keys[mp] = 0xFFFFFFFFFFFFFFFFULL; // keys unique -> one owner
        if (lane == 0) g_src[base + k] = (int)(gm & 0xFFFFFFFFULL);
        __syncwarp();
    }
}

// ---------------- edge geometry: sh, cut, rbf ----------------
__global__ void edge_kernel(const float* __restrict__ x){
    int e = blockIdx.x*blockDim.x + threadIdx.x;
    if (e >= BB*NN*KK) return;
    int b = e / (NN*KK);
    int i = (e / KK) % NN;
    int s = g_src[e];
    const float* pos = x + b*NN*3;
    float vx = pos[3*i]-pos[3*s], vy = pos[3*i+1]-pos[3*s+1], vz = pos[3*i+2]-pos[3*s+2];
    float r = sqrtf(vx*vx + vy*vy + vz*vz);
    float inv = 1.0f / fmaxf(r, 1e-9f);
    float ux = vx*inv, uy = vy*inv, uz = vz*inv;
    float sh[9];
    sh[0] = 1.0f;
    sh[1] = 1.7320508075688772f*ux;
    sh[2] = 1.7320508075688772f*uy;
    sh[3] = 1.7320508075688772f*uz;
    sh[4] = 3.872983346207417f*ux*uy;
    sh[5] = 3.872983346207417f*uy*uz;
    sh[6] = 1.118033988749895f*(3.0f*uz*uz - 1.0f);
    sh[7] = 3.872983346207417f*ux*uz;
    sh[8] = 1.9364916731037085f*(ux*ux - uy*uy);
    #pragma unroll
    for (int m = 0; m < 9; m++) g_sh[e*9+m] = sh[m];
    float arg = 10.0f*(1.0f - r*0.5f);
    float cut = (arg > 0.0f) ? 1.4f*expf(-1.0f/arg) : 0.0f;
    g_cut[e] = cut;
    const float scale = 4.7982245866f; // sqrt(32)*0.95/1.12
    #pragma unroll
    for (int m = 0; m < NBF; m++){
        float c = 2.0f*(float)m/31.0f;
        float d = (r - c)*15.5f;      // /step, step = 2/31
        g_rbf[e*NBF+m] = expf(-d*d)*scale*cut;
    }
}

// ---------------- node embedding: concat(y, t) @ W_embed ----------------
__global__ void embed_kernel(const float* __restrict__ y, const float* __restrict__ t,
                             const float* __restrict__ We){
    int bn = blockIdx.x, c = threadIdx.x;
    int b = bn / NN;
    __shared__ float in[19];
    if (c < 3) in[c] = y[bn*3+c];
    else if (c < 19) in[c] = t[b*TD + c-3];
    __syncthreads();
    float acc = 0.f;
    #pragma unroll
    for (int j = 0; j < 19; j++) acc += in[j]*We[j*DD + c];
    g_node[bn*DD + c] = acc;
}

// ---------------- q = node @ Wq[l] ----------------
__global__ void q_kernel(const float* __restrict__ Wq){
    int bn = blockIdx.x, c = threadIdx.x;
    __shared__ float nd[DD];
    nd[c] = g_node[bn*DD + c];
    __syncthreads();
    float acc = 0.f;
    for (int j = 0; j < DD; j++) acc += nd[j]*Wq[j*DD + c];
    g_q[bn*DD + c] = acc;
}

// ---------------- main attention kernel: one block per (b, node) ----------------
__global__ void attn_kernel(const float* __restrict__ Wk1, const float* __restrict__ bk1,
                            const float* __restrict__ Wk2, const float* __restrict__ Wv,
                            const float* __restrict__ t){
    extern __shared__ float smem[];
    float* sN = smem;                 // [32][256] neighbor features
    float* sE = sN + KK*DD;           // [32][304] E matrix, later reused as kf [32][256]
    float* sH = sE + KK*EIN_;         // [32][128]
    __shared__ float sq[DD];
    __shared__ float sni[NS_];
    __shared__ float ssh[KK*SHD_];
    __shared__ float scut[KK];
    __shared__ int   ssrc[KK];
    __shared__ float slog[KK*NH];
    __shared__ float salpha[KK*NH];
    __shared__ float smax[NH], ssum[NH];

    int bn = blockIdx.x, tid = threadIdx.x;
    int b = bn / NN;
    int ebase = bn*KK;

    sq[tid] = g_q[bn*DD + tid];
    if (tid < NS_) sni[tid] = g_node[bn*DD + tid];
    if (tid < KK) { ssrc[tid] = g_src[ebase + tid]; scut[tid] = g_cut[ebase + tid]; }
    for (int q = tid; q < KK*SHD_; q += 256) ssh[q] = g_sh[ebase*SHD_ + q];
    __syncthreads();

    // gather neighbor node features (coalesced, one row per iter)
    for (int it = 0; it < KK; it++)
        sN[it*DD + tid] = g_node[(b*NN + ssrc[it])*DD + tid];
    __syncthreads();

    // build E = [rbf(32), t(16), nsrc[:128], node_i[:128]]
    for (int q = tid; q < KK*EIN_; q += 256){
        int k = q / EIN_, j = q % EIN_;
        float v;
        if (j < NBF)               v = g_rbf[(ebase+k)*NBF + j];
        else if (j < NBF+TD)       v = t[b*TD + (j - NBF)];
        else if (j < NBF+TD+NS_)   v = sN[k*DD + (j - 48)];
        else                       v = sni[j - 176];
        sE[k*EIN_ + j] = v;
    }
    __syncthreads();

    // GEMM1: h = gelu(E @ Wk1 + b)   [32,304]x[304,128]
    {
        int c = tid & 127, k0 = tid >> 7;
        float acc[16];
        #pragma unroll
        for (int e2 = 0; e2 < 16; e2++) acc[e2] = 0.f;
        const float* W = Wk1 + c;
        for (int j = 0; j < EIN_; j++){
            float w = W[j*HID_];
            #pragma unroll
            for (int e2 = 0; e2 < 16; e2++) acc[e2] += sE[(k0 + 2*e2)*EIN_ + j]*w;
        }
        float bias = bk1[c];
        #pragma unroll
        for (int e2 = 0; e2 < 16; e2++)
            sH[(k0 + 2*e2)*HID_ + c] = gelu_t(acc[e2] + bias);
    }
    __syncthreads();

    // GEMM2: kf = h @ Wk2   [32,128]x[128,256] -> overwrite sE region
    float* sKF = sE;
    {
        int c = tid;
        float acc[32];
        #pragma unroll
        for (int k = 0; k < 32; k++) acc[k] = 0.f;
        const float* W = Wk2 + c;
        for (int j = 0; j < HID_; j++){
            float w = W[j*DD];
            #pragma unroll
            for (int k = 0; k < 32; k++) acc[k] += sH[k*HID_ + j]*w;
        }
        #pragma unroll
        for (int k = 0; k < 32; k++) sKF[k*DD + c] = acc[k];
    }
    __syncthreads();

    // logits: q . kf / sqrt(DH), one (k,h) per thread
    {
        int k = tid >> 3, h = tid & 7;
        float acc = 0.f;
        #pragma unroll
        for (int d = 0; d < DHD; d++) acc += sq[h*DHD + d]*sKF[k*DD + h*DHD + d];
        slog[k*NH + h] = acc*0.17677669529663687f; // 1/sqrt(32)
    }
    __syncthreads();
    if (tid < NH){
        int h = tid;
        float m = -1e30f;
        for (int k = 0; k < KK; k++) m = fmaxf(m, slog[k*NH + h]);
        float s = 0.f;
        for (int k = 0; k < KK; k++) s += scut[k]*expf(slog[k*NH + h] - m);
        smax[h] = m; ssum[h] = s;
    }
    __syncthreads();
    {
        int k = tid >> 3, h = tid & 7;
        salpha[k*NH + h] = scut[k]*expf(slog[k*NH + h] - smax[h]) / (ssum[h] + 1e-9f);
    }
    __syncthreads();

    // GEMM3 + aggregation: v = concat(nsrc, sh) @ Wv ; agg_c = sum_k alpha[k,h]*v[k,c]
    {
        int c = tid;
        float acc[32];
        #pragma unroll
        for (int k = 0; k < 32; k++) acc[k] = 0.f;
        const float* W = Wv + c;
        for (int j = 0; j < DD; j++){
            float w = W[j*DD];
            #pragma unroll
            for (int k = 0; k < 32; k++) acc[k] += sN[k*DD + j]*w;
        }
        #pragma unroll
        for (int j = 0; j < SHD_; j++){
            float w = W[(DD + j)*DD];
            #pragma unroll
            for (int k = 0; k < 32; k++) acc[k] += ssh[k*SHD_ + j]*w;
        }
        int h = c >> 5;
        float out = 0.f;
        #pragma unroll
        for (int k = 0; k < 32; k++) out += salpha[k*NH + h]*acc[k];
        g_agg[bn*DD + c] = out;
    }
}

// ---------------- residual update + scalar activation ----------------
__global__ void update_kernel(const float* __restrict__ Wo){
    int bn = blockIdx.x, c = threadIdx.x;
    __shared__ float ag[DD];
    ag[c] = g_agg[bn*DD + c];
    __syncthreads();
    float acc = g_node[bn*DD + c];
    for (int j = 0; j < DD; j++) acc += ag[j]*Wo[j*DD + c];
    if (c < 64)        acc = gelu_t(acc);
    else if (c < NS_)  acc = tanhf(acc);
    g_node[bn*DD + c] = acc;
}

// ---------------- final projection to 3 ----------------
__global__ void final_kernel(const float* __restrict__ Wo_out, float* __restrict__ out){
    int bn = blockIdx.x, tid = threadIdx.x;
    __shared__ float ag[DD];
    ag[tid] = g_agg[bn*DD + tid];
    __syncthreads();
    if (tid < 3){
        float acc = 0.f;
        for (int j = 0; j < DD; j++) acc += ag[j]*Wo_out[j*3 + tid];
        out[bn*3 + tid] = acc;
    }
}

extern "C" void kernel_launch(void* const* d_in, const int* in_sizes, int n_in,
                              void* d_out, int out_size){
    const float* x      = (const float*)d_in[0];
    const float* y      = (const float*)d_in[1];
    const float* t      = (const float*)d_in[2];
    const float* We     = (const float*)d_in[3];
    const float* Wk1    = (const float*)d_in[4];
    const float* bk1    = (const float*)d_in[5];
    const float* Wk2    = (const float*)d_in[6];
    const float* Wq     = (const float*)d_in[7];
    const float* Wv     = (const float*)d_in[8];
    const float* Wo     = (const float*)d_in[9];
    const float* Wo_out = (const float*)d_in[10];
    float* out = (float*)d_out;

    size_t shmem = (size_t)(KK*DD + KK*EIN_ + KK*HID_)*sizeof(float); // 88064 B
    cudaFuncSetAttribute(attn_kernel, cudaFuncAttributeMaxDynamicSharedMemorySize, (int)shmem);

    knn_kernel<<<dim3(NN, BB), 32>>>(x);
    edge_kernel<<<(BB*NN*KK + 255)/256, 256>>>(x);
    embed_kernel<<<BB*NN, 256>>>(y, t, We);

    for (int l = 0; l < NL; l++){
        q_kernel<<<BB*NN, 256>>>(Wq + (size_t)l*DD*DD);
        attn_kernel<<<BB*NN, 256, shmem>>>(Wk1 + (size_t)l*EIN_*HID_,
                                           bk1 + (size_t)l*HID_,
                                           Wk2 + (size_t)l*HID_*DD,
                                           Wv  + (size_t)l*(DD+SHD_)*DD,
                                           t);
        if (l < NL-1) update_kernel<<<BB*NN, 256>>>(Wo + (size_t)l*DD*DD);
        else          final_kernel<<<BB*NN, 256>>>(Wo_out, out);
    }
}

// round 3
// speedup vs baseline: 1.0026x; 1.0026x over previous
#include <cuda_runtime.h>
#include <math.h>

#define BB   8
#define NN   1024
#define KK   32
#define DD   256
#define NH   8
#define DHD  32
#define TD   16
#define NBF  32
#define HID_ 128
#define NS_  128
#define SHD_ 9
#define EIN_ 304
#define NL   4

// ---- scratch (device globals; no allocation allowed) ----
__device__ int   g_src [BB*NN*KK];
__device__ float g_cut [BB*NN*KK];
__device__ float g_sh  [BB*NN*KK*SHD_];
__device__ float g_rbf [BB*NN*KK*NBF];
__device__ float g_node[BB*NN*DD];
__device__ float g_q   [BB*NN*DD];
__device__ float g_agg [BB*NN*DD];

__device__ __forceinline__ float gelu_t(float x){
    // jax.nn.gelu default (approximate=True, tanh form)
    float x3 = x*x*x;
    return 0.5f*x*(1.0f + tanhf(0.7978845608028654f*(x + 0.044715f*x3)));
}

// ---------------- kNN: one warp per node, select 32 smallest (d2,idx) ----------------
__global__ void knn_kernel(const float* __restrict__ x){
    __shared__ unsigned long long keys[NN];
    int b = blockIdx.y, i = blockIdx.x, lane = threadIdx.x;
    const float* pos = x + b*NN*3;
    float xi = pos[3*i], yi = pos[3*i+1], zi = pos[3*i+2];
    for (int j = lane; j < NN; j += 32){
        float dx = xi - pos[3*j], dy = yi - pos[3*j+1], dz = zi - pos[3*j+2];
        float d2 = dx*dx + dy*dy + dz*dz;
        keys[j] = (((unsigned long long)__float_as_uint(d2)) << 32) | (unsigned int)j;
    }
    __syncwarp();
    int base = (b*NN + i)*KK;
    for (int k = 0; k < KK; k++){
        unsigned long long m = 0xFFFFFFFFFFFFFFFFULL; int mp = -1;
        for (int j = lane; j < NN; j += 32)
            if (keys[j] < m){ m = keys[j]; mp = j; }
        unsigned long long gm = m;
        #pragma unroll
        for (int off = 16; off; off >>= 1){
            unsigned long long o = __shfl_xor_sync(0xFFFFFFFFu, gm, off);
            if (o < gm) gm = o;
        }
        if (m == gm && mp >= 0) keys[mp] = 0xFFFFFFFFFFFFFFFFULL; // keys unique -> one owner
        if (lane == 0) g_src[base + k] = (int)(gm & 0xFFFFFFFFULL);
        __syncwarp();
    }
}

// ---------------- edge geometry: sh, cut, rbf ----------------
__global__ void edge_kernel(const float* __restrict__ x){
    int e = blockIdx.x*blockDim.x + threadIdx.x;
    if (e >= BB*NN*KK) return;
    int b = e / (NN*KK);
    int i = (e / KK) % NN;
    int s = g_src[e];
    const float* pos = x + b*NN*3;
    float vx = pos[3*i]-pos[3*s], vy = pos[3*i+1]-pos[3*s+1], vz = pos[3*i+2]-pos[3*s+2];
    float r = sqrtf(vx*vx + vy*vy + vz*vz);
    float inv = 1.0f / fmaxf(r, 1e-9f);
    float ux = vx*inv, uy = vy*inv, uz = vz*inv;
    float sh[9];
    sh[0] = 1.0f;
    sh[1] = 1.7320508075688772f*ux;
    sh[2] = 1.7320508075688772f*uy;
    sh[3] = 1.7320508075688772f*uz;
    sh[4] = 3.872983346207417f*ux*uy;
    sh[5] = 3.872983346207417f*uy*uz;
    sh[6] = 1.118033988749895f*(3.0f*uz*uz - 1.0f);
    sh[7] = 3.872983346207417f*ux*uz;
    sh[8] = 1.9364916731037085f*(ux*ux - uy*uy);
    #pragma unroll
    for (int m = 0; m < 9; m++) g_sh[e*9+m] = sh[m];
    float arg = 10.0f*(1.0f - r*0.5f);
    float cut = (arg > 0.0f) ? 1.4f*expf(-1.0f/arg) : 0.0f;
    g_cut[e] = cut;
    const float scale = 4.7982245866f; // sqrt(32)*0.95/1.12
    #pragma unroll
    for (int m = 0; m < NBF; m++){
        float c = 2.0f*(float)m/31.0f;
        float d = (r - c)*15.5f;      // /step, step = 2/31
        g_rbf[e*NBF+m] = expf(-d*d)*scale*cut;
    }
}

// ---------------- node embedding: concat(y, t) @ W_embed ----------------
__global__ void embed_kernel(const float* __restrict__ y, const float* __restrict__ t,
                             const float* __restrict__ We){
    int bn = blockIdx.x, c = threadIdx.x;
    int b = bn / NN;
    __shared__ float in[19];
    if (c < 3) in[c] = y[bn*3+c];
    else if (c < 19) in[c] = t[b*TD + c-3];
    __syncthreads();
    float acc = 0.f;
    #pragma unroll
    for (int j = 0; j < 19; j++) acc += in[j]*We[j*DD + c];
    g_node[bn*DD + c] = acc;
}

// ---------------- q = node @ Wq[l] ----------------
__global__ void q_kernel(const float* __restrict__ Wq){
    int bn = blockIdx.x, c = threadIdx.x;
    __shared__ float nd[DD];
    nd[c] = g_node[bn*DD + c];
    __syncthreads();
    float acc = 0.f;
    for (int j = 0; j < DD; j++) acc += nd[j]*Wq[j*DD + c];
    g_q[bn*DD + c] = acc;
}

// ---------------- main attention kernel: one block per (b, node) ----------------
__global__ void attn_kernel(const float* __restrict__ Wk1, const float* __restrict__ bk1,
                            const float* __restrict__ Wk2, const float* __restrict__ Wv,
                            const float* __restrict__ t){
    extern __shared__ float smem[];
    float* sN = smem;                 // [32][256] neighbor features
    float* sE = sN + KK*DD;           // [32][304] E matrix, later reused as kf [32][256]
    float* sH = sE + KK*EIN_;         // [32][128]
    __shared__ float sq[DD];
    __shared__ float sni[NS_];
    __shared__ float ssh[KK*SHD_];
    __shared__ float scut[KK];
    __shared__ int   ssrc[KK];
    __shared__ float slog[KK*NH];
    __shared__ float salpha[KK*NH];
    __shared__ float smax[NH], ssum[NH];

    int bn = blockIdx.x, tid = threadIdx.x;
    int b = bn / NN;
    int ebase = bn*KK;

    sq[tid] = g_q[bn*DD + tid];
    if (tid < NS_) sni[tid] = g_node[bn*DD + tid];
    if (tid < KK) { ssrc[tid] = g_src[ebase + tid]; scut[tid] = g_cut[ebase + tid]; }
    for (int q = tid; q < KK*SHD_; q += 256) ssh[q] = g_sh[ebase*SHD_ + q];
    __syncthreads();

    // gather neighbor node features (coalesced, one row per iter)
    for (int it = 0; it < KK; it++)
        sN[it*DD + tid] = g_node[(b*NN + ssrc[it])*DD + tid];
    __syncthreads();

    // build E = [rbf(32), t(16), nsrc[:128], node_i[:128]]
    for (int q = tid; q < KK*EIN_; q += 256){
        int k = q / EIN_, j = q % EIN_;
        float v;
        if (j < NBF)               v = g_rbf[(ebase+k)*NBF + j];
        else if (j < NBF+TD)       v = t[b*TD + (j - NBF)];
        else if (j < NBF+TD+NS_)   v = sN[k*DD + (j - 48)];
        else                       v = sni[j - 176];
        sE[k*EIN_ + j] = v;
    }
    __syncthreads();

    // GEMM1: h = gelu(E @ Wk1 + b)   [32,304]x[304,128]
    {
        int c = tid & 127, k0 = tid >> 7;
        float acc[16];
        #pragma unroll
        for (int e2 = 0; e2 < 16; e2++) acc[e2] = 0.f;
        const float* W = Wk1 + c;
        for (int j = 0; j < EIN_; j++){
            float w = W[j*HID_];
            #pragma unroll
            for (int e2 = 0; e2 < 16; e2++) acc[e2] += sE[(k0 + 2*e2)*EIN_ + j]*w;
        }
        float bias = bk1[c];
        #pragma unroll
        for (int e2 = 0; e2 < 16; e2++)
            sH[(k0 + 2*e2)*HID_ + c] = gelu_t(acc[e2] + bias);
    }
    __syncthreads();

    // GEMM2: kf = h @ Wk2   [32,128]x[128,256] -> overwrite sE region
    float* sKF = sE;
    {
        int c = tid;
        float acc[32];
        #pragma unroll
        for (int k = 0; k < 32; k++) acc[k] = 0.f;
        const float* W = Wk2 + c;
        for (int j = 0; j < HID_; j++){
            float w = W[j*DD];
            #pragma unroll
            for (int k = 0; k < 32; k++) acc[k] += sH[k*HID_ + j]*w;
        }
        #pragma unroll
        for (int k = 0; k < 32; k++) sKF[k*DD + c] = acc[k];
    }
    __syncthreads();

    // logits: q . kf / sqrt(DH), one (k,h) per thread
    {
        int k = tid >> 3, h = tid & 7;
        float acc = 0.f;
        #pragma unroll
        for (int d = 0; d < DHD; d++) acc += sq[h*DHD + d]*sKF[k*DD + h*DHD + d];
        slog[k*NH + h] = acc*0.17677669529663687f; // 1/sqrt(32)
    }
    __syncthreads();
    if (tid < NH){
        int h = tid;
        float m = -1e30f;
        for (int k = 0; k < KK; k++) m = fmaxf(m, slog[k*NH + h]);
        float s = 0.f;
        for (int k = 0; k < KK; k++) s += scut[k]*expf(slog[k*NH + h] - m);
        smax[h] = m; ssum[h] = s;
    }
    __syncthreads();
    {
        int k = tid >> 3, h = tid & 7;
        salpha[k*NH + h] = scut[k]*expf(slog[k*NH + h] - smax[h]) / (ssum[h] + 1e-9f);
    }
    __syncthreads();

    // GEMM3 + aggregation: v = concat(nsrc, sh) @ Wv ; agg_c = sum_k alpha[k,h]*v[k,c]
    {
        int c = tid;
        float acc[32];
        #pragma unroll
        for (int k = 0; k < 32; k++) acc[k] = 0.f;
        const float* W = Wv + c;
        for (int j = 0; j < DD; j++){
            float w = W[j*DD];
            #pragma unroll
            for (int k = 0; k < 32; k++) acc[k] += sN[k*DD + j]*w;
        }
        #pragma unroll
        for (int j = 0; j < SHD_; j++){
            float w = W[(DD + j)*DD];
            #pragma unroll
            for (int k = 0; k < 32; k++) acc[k] += ssh[k*SHD_ + j]*w;
        }
        int h = c >> 5;
        float out = 0.f;
        #pragma unroll
        for (int k = 0; k < 32; k++) out += salpha[k*NH + h]*acc[k];
        g_agg[bn*DD + c] = out;
    }
}

// ---------------- residual update + scalar activation ----------------
__global__ void update_kernel(const float* __restrict__ Wo){
    int bn = blockIdx.x, c = threadIdx.x;
    __shared__ float ag[DD];
    ag[c] = g_agg[bn*DD + c];
    __syncthreads();
    float acc = g_node[bn*DD + c];
    for (int j = 0; j < DD; j++) acc += ag[j]*Wo[j*DD + c];
    if (c < 64)        acc = gelu_t(acc);
    else if (c < NS_)  acc = tanhf(acc);
    g_node[bn*DD + c] = acc;
}

// ---------------- final projection to 3 ----------------
__global__ void final_kernel(const float* __restrict__ Wo_out, float* __restrict__ out){
    int bn = blockIdx.x, tid = threadIdx.x;
    __shared__ float ag[DD];
    ag[tid] = g_agg[bn*DD + tid];
    __syncthreads();
    if (tid < 3){
        float acc = 0.f;
        for (int j = 0; j < DD; j++) acc += ag[j]*Wo_out[j*3 + tid];
        out[bn*3 + tid] = acc;
    }
}

extern "C" void kernel_launch(void* const* d_in, const int* in_sizes, int n_in,
                              void* d_out, int out_size){
    const float* x      = (const float*)d_in[0];
    const float* y      = (const float*)d_in[1];
    const float* t      = (const float*)d_in[2];
    const float* We     = (const float*)d_in[3];
    const float* Wk1    = (const float*)d_in[4];
    const float* bk1    = (const float*)d_in[5];
    const float* Wk2    = (const float*)d_in[6];
    const float* Wq     = (const float*)d_in[7];
    const float* Wv     = (const float*)d_in[8];
    const float* Wo     = (const float*)d_in[9];
    const float* Wo_out = (const float*)d_in[10];
    float* out = (float*)d_out;

    size_t shmem = (size_t)(KK*DD + KK*EIN_ + KK*HID_)*sizeof(float); // 88064 B
    cudaFuncSetAttribute(attn_kernel, cudaFuncAttributeMaxDynamicSharedMemorySize, (int)shmem);

    knn_kernel<<<dim3(NN, BB), 32>>>(x);
    edge_kernel<<<(BB*NN*KK + 255)/256, 256>>>(x);
    embed_kernel<<<BB*NN, 256>>>(y, t, We);

    for (int l = 0; l < NL; l++){
        q_kernel<<<BB*NN, 256>>>(Wq + (size_t)l*DD*DD);
        attn_kernel<<<BB*NN, 256, shmem>>>(Wk1 + (size_t)l*EIN_*HID_,
                                           bk1 + (size_t)l*HID_,
                                           Wk2 + (size_t)l*HID_*DD,
                                           Wv  + (size_t)l*(DD+SHD_)*DD,
                                           t);
        if (l < NL-1) update_kernel<<<BB*NN, 256>>>(Wo + (size_t)l*DD*DD);
        else          final_kernel<<<BB*NN, 256>>>(Wo_out, out);
    }
}

// round 4
// speedup vs baseline: 9.3363x; 9.3123x over previous
#include <cuda_runtime.h>
#include <math.h>

#define BB   8
#define NN   1024
#define KK   32
#define DD   256
#define NH   8
#define DHD  32
#define TD   16
#define NBF  32
#define HID_ 128
#define NS_  128
#define SHD_ 9
#define EIN_ 304
#define NL   4

// ---- scratch (device globals; no allocation allowed) ----
__device__ int   g_src [BB*NN*KK];
__device__ float g_cut [BB*NN*KK];
__device__ float g_sh  [BB*NN*KK*SHD_];
__device__ float g_rbf [BB*NN*KK*NBF];
__device__ float g_node[BB*NN*DD];
__device__ float g_q   [BB*NN*DD];
__device__ float g_ks  [BB*NN*HID_];
__device__ float g_kd  [BB*NN*HID_];
__device__ float g_vs  [BB*NN*DD];
__device__ float g_agg [BB*NN*DD];

__device__ __forceinline__ float gelu_t(float x){
    // jax.nn.gelu default (approximate=True, tanh form)
    float x3 = x*x*x;
    return 0.5f*x*(1.0f + tanhf(0.7978845608028654f*(x + 0.044715f*x3)));
}

// ---------------- kNN: one warp per node, select 32 smallest (d2,idx) ----------------
__global__ void knn_kernel(const float* __restrict__ x){
    __shared__ unsigned long long keys[NN];
    int b = blockIdx.y, i = blockIdx.x, lane = threadIdx.x;
    const float* pos = x + b*NN*3;
    float xi = pos[3*i], yi = pos[3*i+1], zi = pos[3*i+2];
    for (int j = lane; j < NN; j += 32){
        float dx = xi - pos[3*j], dy = yi - pos[3*j+1], dz = zi - pos[3*j+2];
        float d2 = dx*dx + dy*dy + dz*dz;
        keys[j] = (((unsigned long long)__float_as_uint(d2)) << 32) | (unsigned int)j;
    }
    __syncwarp();
    int base = (b*NN + i)*KK;
    for (int k = 0; k < KK; k++){
        unsigned long long m = 0xFFFFFFFFFFFFFFFFULL; int mp = -1;
        for (int j = lane; j < NN; j += 32)
            if (keys[j] < m){ m = keys[j]; mp = j; }
        unsigned long long gm = m;
        #pragma unroll
        for (int off = 16; off; off >>= 1){
            unsigned long long o = __shfl_xor_sync(0xFFFFFFFFu, gm, off);
            if (o < gm) gm = o;
        }
        if (m == gm && mp >= 0) keys[mp] = 0xFFFFFFFFFFFFFFFFULL; // keys unique -> one owner
        if (lane == 0) g_src[base + k] = (int)(gm & 0xFFFFFFFFULL);
        __syncwarp();
    }
}

// ---------------- edge geometry: sh, cut, rbf ----------------
__global__ void edge_kernel(const float* __restrict__ x){
    int e = blockIdx.x*blockDim.x + threadIdx.x;
    if (e >= BB*NN*KK) return;
    int b = e / (NN*KK);
    int i = (e / KK) % NN;
    int s = g_src[e];
    const float* pos = x + b*NN*3;
    float vx = pos[3*i]-pos[3*s], vy = pos[3*i+1]-pos[3*s+1], vz = pos[3*i+2]-pos[3*s+2];
    float r = sqrtf(vx*vx + vy*vy + vz*vz);
    float inv = 1.0f / fmaxf(r, 1e-9f);
    float ux = vx*inv, uy = vy*inv, uz = vz*inv;
    float sh[9];
    sh[0] = 1.0f;
    sh[1] = 1.7320508075688772f*ux;
    sh[2] = 1.7320508075688772f*uy;
    sh[3] = 1.7320508075688772f*uz;
    sh[4] = 3.872983346207417f*ux*uy;
    sh[5] = 3.872983346207417f*uy*uz;
    sh[6] = 1.118033988749895f*(3.0f*uz*uz - 1.0f);
    sh[7] = 3.872983346207417f*ux*uz;
    sh[8] = 1.9364916731037085f*(ux*ux - uy*uy);
    #pragma unroll
    for (int m = 0; m < 9; m++) g_sh[e*9+m] = sh[m];
    float arg = 10.0f*(1.0f - r*0.5f);
    float cut = (arg > 0.0f) ? 1.4f*expf(-1.0f/arg) : 0.0f;
    g_cut[e] = cut;
    const float scale = 4.7982245866f; // sqrt(32)*0.95/1.12
    #pragma unroll
    for (int m = 0; m < NBF; m++){
        float c = 2.0f*(float)m/31.0f;
        float d = (r - c)*15.5f;      // /step, step = 2/31
        g_rbf[e*NBF+m] = expf(-d*d)*scale*cut;
    }
}

// ---------------- node embedding: concat(y, t) @ W_embed ----------------
__global__ void embed_kernel(const float* __restrict__ y, const float* __restrict__ t,
                             const float* __restrict__ We){
    int bn = blockIdx.x, c = threadIdx.x;
    int b = bn / NN;
    __shared__ float in[19];
    if (c < 3) in[c] = y[bn*3+c];
    else if (c < 19) in[c] = t[b*TD + c-3];
    __syncthreads();
    float acc = 0.f;
    #pragma unroll
    for (int j = 0; j < 19; j++) acc += in[j]*We[j*DD + c];
    g_node[bn*DD + c] = acc;
}

// ---------------- per-node projections for layer l ----------------
// q  = node @ Wq                               [256]
// vs = node @ Wv[0:256]                        [256]
// ks = node[:128] @ Wk1[48:176]                [128]
// kd = node[:128] @ Wk1[176:304] + t @ Wk1[32:48] + bk1   [128]
__global__ void nodeproj_kernel(const float* __restrict__ Wq,
                                const float* __restrict__ Wk1,
                                const float* __restrict__ bk1,
                                const float* __restrict__ Wv,
                                const float* __restrict__ t){
    __shared__ float nd[DD];
    __shared__ float st[TD];
    int bn = blockIdx.x, c = threadIdx.x, b = bn/NN;
    nd[c] = g_node[bn*DD + c];
    if (c < TD) st[c] = t[b*TD + c];
    __syncthreads();
    float accq = 0.f, accv = 0.f;
    #pragma unroll 4
    for (int j = 0; j < DD; j++){
        float n = nd[j];
        accq += n*Wq[j*DD + c];
        accv += n*Wv[j*DD + c];
    }
    g_q [bn*DD + c] = accq;
    g_vs[bn*DD + c] = accv;
    if (c < HID_){
        float a = 0.f;
        #pragma unroll 4
        for (int j = 0; j < HID_; j++) a += nd[j]*Wk1[(48+j)*HID_ + c];
        g_ks[bn*HID_ + c] = a;
    } else {
        int cc = c - HID_;
        float a = bk1[cc];
        #pragma unroll
        for (int j = 0; j < TD; j++) a += st[j]*Wk1[(32+j)*HID_ + cc];
        #pragma unroll 4
        for (int j = 0; j < HID_; j++) a += nd[j]*Wk1[(176+j)*HID_ + cc];
        g_kd[bn*HID_ + cc] = a;
    }
}

// ---------------- main attention kernel: one block per (b, node) ----------------
__global__ void attn_kernel(const float* __restrict__ Wk1,   // W_r = rows [0:32)
                            const float* __restrict__ Wk2,   // [128,256]
                            const float* __restrict__ WvSh){ // Wv rows [256:265)
    __shared__ float skd[HID_];
    __shared__ float sq[DD];
    __shared__ float sqk[HID_*NH];      // [j*8 + h]
    __shared__ float srbf[KK*NBF];
    __shared__ float ssh[KK*SHD_];
    __shared__ float scut[KK];
    __shared__ int   ssrc[KK];          // GLOBAL node index (b*NN + src)
    __shared__ float sH[KK*129];        // padded stride 129
    __shared__ float slog[KK*NH];
    __shared__ float salpha[KK*NH];
    __shared__ float smax[NH], ssum[NH];
    __shared__ float shw[NH*SHD_];

    int bn = blockIdx.x, tid = threadIdx.x;
    int b = bn / NN;
    int ebase = bn*KK;

    sq[tid] = g_q[bn*DD + tid];
    if (tid < HID_) skd[tid] = g_kd[bn*HID_ + tid];
    if (tid < KK){ ssrc[tid] = b*NN + g_src[ebase + tid]; scut[tid] = g_cut[ebase + tid]; }
    for (int q = tid; q < KK*NBF;  q += 256) srbf[q] = g_rbf[ebase*NBF  + q];
    for (int q = tid; q < KK*SHD_; q += 256) ssh[q]  = g_sh [ebase*SHD_ + q];
    __syncthreads();

    // h[k,c] = gelu(kd[c] + ks[src_k][c] + rbf[k] @ W_r[:,c])
    {
        int c = tid & 127, k0 = tid >> 7;     // k0: 0/1 -> rows k0*16..k0*16+15
        float acc[16];
        #pragma unroll
        for (int i = 0; i < 16; i++){
            int k = k0*16 + i;
            acc[i] = skd[c] + g_ks[ssrc[k]*HID_ + c];
        }
        for (int j = 0; j < NBF; j++){
            float w = Wk1[j*HID_ + c];
            #pragma unroll
            for (int i = 0; i < 16; i++) acc[i] += srbf[(k0*16+i)*NBF + j]*w;
        }
        #pragma unroll
        for (int i = 0; i < 16; i++)
            sH[(k0*16+i)*129 + c] = gelu_t(acc[i]);
    }

    // qk[j,h] = sum_{c in head h} q[c]*Wk2[j,c]   (warp w owns j = w*16+jj)
    {
        int w = tid >> 5, lane = tid & 31;
        int h = lane >> 2, cq = lane & 3;     // lane covers c = lane*8 .. lane*8+7
        #pragma unroll
        for (int jj = 0; jj < 16; jj++){
            int j = w*16 + jj;
            const float4* W4 = reinterpret_cast<const float4*>(Wk2 + j*DD + lane*8);
            float4 w0 = W4[0], w1 = W4[1];
            const float* qv = sq + lane*8;
            float acc = w0.x*qv[0] + w0.y*qv[1] + w0.z*qv[2] + w0.w*qv[3]
                      + w1.x*qv[4] + w1.y*qv[5] + w1.z*qv[6] + w1.w*qv[7];
            acc += __shfl_xor_sync(0xFFFFFFFFu, acc, 1);
            acc += __shfl_xor_sync(0xFFFFFFFFu, acc, 2);
            if (cq == 0) sqk[j*NH + h] = acc;
        }
    }
    __syncthreads();

    // logits[k,h] = (1/sqrt(32)) sum_j h[k,j]*qk[j,h]
    {
        int k = tid >> 3, h = tid & 7;
        float acc = 0.f;
        #pragma unroll 8
        for (int j = 0; j < HID_; j++) acc += sH[k*129 + j]*sqk[j*NH + h];
        slog[k*NH + h] = acc*0.17677669529663687f;
    }
    __syncthreads();
    if (tid < NH){
        int h = tid;
        float m = -1e30f;
        for (int k = 0; k < KK; k++) m = fmaxf(m, slog[k*NH + h]);
        float s = 0.f;
        for (int k = 0; k < KK; k++) s += scut[k]*expf(slog[k*NH + h] - m);
        smax[h] = m; ssum[h] = s;
    }
    __syncthreads();
    {
        int k = tid >> 3, h = tid & 7;
        salpha[k*NH + h] = scut[k]*expf(slog[k*NH + h] - smax[h]) / (ssum[h] + 1e-9f);
    }
    __syncthreads();
    // shw[h,j] = sum_k alpha[k,h]*sh[k,j]
    if (tid < NH*SHD_){
        int h = tid / SHD_, j = tid % SHD_;
        float s = 0.f;
        for (int k = 0; k < KK; k++) s += salpha[k*NH + h]*ssh[k*SHD_ + j];
        shw[tid] = s;
    }
    __syncthreads();
    // agg[c] = sum_k alpha[k,h]*vs[src_k][c] + sum_j shw[h,j]*WvSh[j,c]
    {
        int c = tid, h = c >> 5;
        float out = 0.f;
        #pragma unroll
        for (int j = 0; j < SHD_; j++) out += shw[h*SHD_ + j]*WvSh[j*DD + c];
        #pragma unroll 8
        for (int k = 0; k < KK; k++) out += salpha[k*NH + h]*g_vs[ssrc[k]*DD + c];
        g_agg[bn*DD + c] = out;
    }
}

// ---------------- residual update + scalar activation ----------------
__global__ void update_kernel(const float* __restrict__ Wo){
    int bn = blockIdx.x, c = threadIdx.x;
    __shared__ float ag[DD];
    ag[c] = g_agg[bn*DD + c];
    __syncthreads();
    float acc = g_node[bn*DD + c];
    #pragma unroll 4
    for (int j = 0; j < DD; j++) acc += ag[j]*Wo[j*DD + c];
    if (c < 64)        acc = gelu_t(acc);
    else if (c < NS_)  acc = tanhf(acc);
    g_node[bn*DD + c] = acc;
}

// ---------------- final projection to 3 ----------------
__global__ void final_kernel(const float* __restrict__ Wo_out, float* __restrict__ out){
    int bn = blockIdx.x, tid = threadIdx.x;
    __shared__ float ag[DD];
    ag[tid] = g_agg[bn*DD + tid];
    __syncthreads();
    if (tid < 3){
        float acc = 0.f;
        for (int j = 0; j < DD; j++) acc += ag[j]*Wo_out[j*3 + tid];
        out[bn*3 + tid] = acc;
    }
}

extern "C" void kernel_launch(void* const* d_in, const int* in_sizes, int n_in,
                              void* d_out, int out_size){
    const float* x      = (const float*)d_in[0];
    const float* y      = (const float*)d_in[1];
    const float* t      = (const float*)d_in[2];
    const float* We     = (const float*)d_in[3];
    const float* Wk1    = (const float*)d_in[4];
    const float* bk1    = (const float*)d_in[5];
    const float* Wk2    = (const float*)d_in[6];
    const float* Wq     = (const float*)d_in[7];
    const float* Wv     = (const float*)d_in[8];
    const float* Wo     = (const float*)d_in[9];
    const float* Wo_out = (const float*)d_in[10];
    float* out = (float*)d_out;

    knn_kernel<<<dim3(NN, BB), 32>>>(x);
    edge_kernel<<<(BB*NN*KK + 255)/256, 256>>>(x);
    embed_kernel<<<BB*NN, 256>>>(y, t, We);

    for (int l = 0; l < NL; l++){
        const float* Wk1_l = Wk1 + (size_t)l*EIN_*HID_;
        const float* Wv_l  = Wv  + (size_t)l*(DD+SHD_)*DD;
        nodeproj_kernel<<<BB*NN, 256>>>(Wq + (size_t)l*DD*DD, Wk1_l,
                                        bk1 + (size_t)l*HID_, Wv_l, t);
        attn_kernel<<<BB*NN, 256>>>(Wk1_l, Wk2 + (size_t)l*HID_*DD,
                                    Wv_l + (size_t)DD*DD);
        if (l < NL-1) update_kernel<<<BB*NN, 256>>>(Wo + (size_t)l*DD*DD);
        else          final_kernel<<<BB*NN, 256>>>(Wo_out, out);
    }
}

// round 6
// speedup vs baseline: 10.4427x; 1.1185x over previous
#include <cuda_runtime.h>
#include <math.h>

#define BB   8
#define NN   1024
#define KK   32
#define DD   256
#define NH   8
#define DHD  32
#define TD   16
#define NBF  32
#define HID_ 128
#define NS_  128
#define SHD_ 9
#define EIN_ 304
#define NL   4
#define MT   16      // nodes per nodeproj block
#define QKW  (HID_*NH)   // 1024

// ---- scratch (device globals; no allocation allowed) ----
__device__ int   g_src [BB*NN*KK];
__device__ float g_cut [BB*NN*KK];
__device__ float g_sh  [BB*NN*KK*SHD_];
__device__ float g_rbf [BB*NN*KK*NBF];
__device__ float g_node[BB*NN*DD];
__device__ float g_ks  [BB*NN*HID_];
__device__ float g_kd  [BB*NN*HID_];
__device__ float g_vs  [BB*NN*DD];
__device__ float g_qk  [BB*NN*QKW];
__device__ float g_agg [BB*NN*DD];

__device__ __forceinline__ float gelu_t(float x){
    float x3 = x*x*x;
    return 0.5f*x*(1.0f + tanhf(0.7978845608028654f*(x + 0.044715f*x3)));
}

// 16 FFMA fed by 4 broadcast LDS.128 from transposed tile row
#define FMA16(acc, base, w) { \
    const float4* _v4 = reinterpret_cast<const float4*>(base); \
    float4 _a0=_v4[0], _a1=_v4[1], _a2=_v4[2], _a3=_v4[3]; \
    acc[0]+=_a0.x*(w); acc[1]+=_a0.y*(w); acc[2]+=_a0.z*(w); acc[3]+=_a0.w*(w); \
    acc[4]+=_a1.x*(w); acc[5]+=_a1.y*(w); acc[6]+=_a1.z*(w); acc[7]+=_a1.w*(w); \
    acc[8]+=_a2.x*(w); acc[9]+=_a2.y*(w); acc[10]+=_a2.z*(w); acc[11]+=_a2.w*(w); \
    acc[12]+=_a3.x*(w); acc[13]+=_a3.y*(w); acc[14]+=_a3.z*(w); acc[15]+=_a3.w*(w); }

// ---------------- kNN: one warp per node, select 32 smallest (d2,idx) ----------------
__global__ void knn_kernel(const float* __restrict__ x){
    __shared__ unsigned long long keys[NN];
    int b = blockIdx.y, i = blockIdx.x, lane = threadIdx.x;
    const float* pos = x + b*NN*3;
    float xi = pos[3*i], yi = pos[3*i+1], zi = pos[3*i+2];
    for (int j = lane; j < NN; j += 32){
        float dx = xi - pos[3*j], dy = yi - pos[3*j+1], dz = zi - pos[3*j+2];
        float d2 = dx*dx + dy*dy + dz*dz;
        keys[j] = (((unsigned long long)__float_as_uint(d2)) << 32) | (unsigned int)j;
    }
    __syncwarp();
    int base = (b*NN + i)*KK;
    for (int k = 0; k < KK; k++){
        unsigned long long m = 0xFFFFFFFFFFFFFFFFULL; int mp = -1;
        for (int j = lane; j < NN; j += 32)
            if (keys[j] < m){ m = keys[j]; mp = j; }
        unsigned long long gm = m;
        #pragma unroll
        for (int off = 16; off; off >>= 1){
            unsigned long long o = __shfl_xor_sync(0xFFFFFFFFu, gm, off);
            if (o < gm) gm = o;
        }
        if (m == gm && mp >= 0) keys[mp] = 0xFFFFFFFFFFFFFFFFULL;
        if (lane == 0) g_src[base + k] = (int)(gm & 0xFFFFFFFFULL);
        __syncwarp();
    }
}

// ---------------- edge geometry: sh, cut, rbf ----------------
__global__ void edge_kernel(const float* __restrict__ x){
    int e = blockIdx.x*blockDim.x + threadIdx.x;
    if (e >= BB*NN*KK) return;
    int b = e / (NN*KK);
    int i = (e / KK) % NN;
    int s = g_src[e];
    const float* pos = x + b*NN*3;
    float vx = pos[3*i]-pos[3*s], vy = pos[3*i+1]-pos[3*s+1], vz = pos[3*i+2]-pos[3*s+2];
    float r = sqrtf(vx*vx + vy*vy + vz*vz);
    float inv = 1.0f / fmaxf(r, 1e-9f);
    float ux = vx*inv, uy = vy*inv, uz = vz*inv;
    float sh[9];
    sh[0] = 1.0f;
    sh[1] = 1.7320508075688772f*ux;
    sh[2] = 1.7320508075688772f*uy;
    sh[3] = 1.7320508075688772f*uz;
    sh[4] = 3.872983346207417f*ux*uy;
    sh[5] = 3.872983346207417f*uy*uz;
    sh[6] = 1.118033988749895f*(3.0f*uz*uz - 1.0f);
    sh[7] = 3.872983346207417f*ux*uz;
    sh[8] = 1.9364916731037085f*(ux*ux - uy*uy);
    #pragma unroll
    for (int m = 0; m < 9; m++) g_sh[e*9+m] = sh[m];
    float arg = 10.0f*(1.0f - r*0.5f);
    float cut = (arg > 0.0f) ? 1.4f*expf(-1.0f/arg) : 0.0f;
    g_cut[e] = cut;
    const float scale = 4.7982245866f; // sqrt(32)*0.95/1.12
    #pragma unroll
    for (int m = 0; m < NBF; m++){
        float c = 2.0f*(float)m/31.0f;
        float d = (r - c)*15.5f;
        g_rbf[e*NBF+m] = expf(-d*d)*scale*cut;
    }
}

// ---------------- node embedding ----------------
__global__ void embed_kernel(const float* __restrict__ y, const float* __restrict__ t,
                             const float* __restrict__ We){
    int bn = blockIdx.x, c = threadIdx.x;
    int b = bn / NN;
    __shared__ float in[19];
    if (c < 3) in[c] = y[bn*3+c];
    else if (c < 19) in[c] = t[b*TD + c-3];
    __syncthreads();
    float acc = 0.f;
    #pragma unroll
    for (int j = 0; j < 19; j++) acc += in[j]*We[j*DD + c];
    g_node[bn*DD + c] = acc;
}

// ---------------- per-node work, 16 nodes per block ----------------
// (optional fused update) node = act(node + agg @ Wo)
// q  = node @ Wq  (kept in smem only)
// vs = node @ Wv[0:256]
// ks = node[:128] @ Wk1[48:176]
// kd = node[:128] @ Wk1[176:304] + t @ Wk1[32:48] + bk1
// qk[h,j] = sum_{dh} q[h*32+dh] * Wk2[j, h*32+dh]
__global__ void __launch_bounds__(256) nodeproj_kernel(
        const float* __restrict__ Wq,  const float* __restrict__ Wk1,
        const float* __restrict__ bk1, const float* __restrict__ Wk2,
        const float* __restrict__ Wv,  const float* __restrict__ Wo,
        const float* __restrict__ t){
    __shared__ float sX[DD*20];     // transposed tile [j][m], pad 20
    __shared__ float sQ[MT*DD];     // q per node [m][c]
    __shared__ float st[TD];
    int c = threadIdx.x;
    int bn0 = blockIdx.x*MT;
    int b = bn0 / NN;
    if (c < TD) st[c] = t[b*TD + c];

    if (Wo){
        // fused residual update: stage agg transposed, then node = act(node + agg@Wo)
        #pragma unroll
        for (int m = 0; m < MT; m++) sX[c*20 + m] = g_agg[(bn0+m)*DD + c];
        __syncthreads();
        float acc[MT];
        #pragma unroll
        for (int m = 0; m < MT; m++) acc[m] = g_node[(bn0+m)*DD + c];
        for (int j = 0; j < DD; j++){
            float w = Wo[j*DD + c];
            FMA16(acc, sX + j*20, w);
        }
        #pragma unroll
        for (int m = 0; m < MT; m++){
            float v = acc[m];
            if (c < 64)       v = gelu_t(v);
            else if (c < NS_) v = tanhf(v);
            acc[m] = v;
            g_node[(bn0+m)*DD + c] = v;
        }
        __syncthreads();
        #pragma unroll
        for (int m = 0; m < MT; m++) sX[c*20 + m] = acc[m];
    } else {
        #pragma unroll
        for (int m = 0; m < MT; m++) sX[c*20 + m] = g_node[(bn0+m)*DD + c];
    }
    __syncthreads();

    // q + vs
    {
        float aq[MT], av[MT];
        #pragma unroll
        for (int m = 0; m < MT; m++){ aq[m] = 0.f; av[m] = 0.f; }
        for (int j = 0; j < DD; j++){
            float wq = Wq[j*DD + c];
            float wv = Wv[j*DD + c];
            const float4* v4 = reinterpret_cast<const float4*>(sX + j*20);
            float4 a0=v4[0], a1=v4[1], a2=v4[2], a3=v4[3];
            aq[0]+=a0.x*wq; av[0]+=a0.x*wv;  aq[1]+=a0.y*wq; av[1]+=a0.y*wv;
            aq[2]+=a0.z*wq; av[2]+=a0.z*wv;  aq[3]+=a0.w*wq; av[3]+=a0.w*wv;
            aq[4]+=a1.x*wq; av[4]+=a1.x*wv;  aq[5]+=a1.y*wq; av[5]+=a1.y*wv;
            aq[6]+=a1.z*wq; av[6]+=a1.z*wv;  aq[7]+=a1.w*wq; av[7]+=a1.w*wv;
            aq[8]+=a2.x*wq; av[8]+=a2.x*wv;  aq[9]+=a2.y*wq; av[9]+=a2.y*wv;
            aq[10]+=a2.z*wq; av[10]+=a2.z*wv; aq[11]+=a2.w*wq; av[11]+=a2.w*wv;
            aq[12]+=a3.x*wq; av[12]+=a3.x*wv; aq[13]+=a3.y*wq; av[13]+=a3.y*wv;
            aq[14]+=a3.z*wq; av[14]+=a3.z*wv; aq[15]+=a3.w*wq; av[15]+=a3.w*wv;
        }
        #pragma unroll
        for (int m = 0; m < MT; m++){
            g_vs[(bn0+m)*DD + c] = av[m];
            sQ[m*DD + c] = aq[m];
        }
    }
    __syncthreads();

    // ks / kd (split threads)
    if (c < HID_){
        float a[MT];
        #pragma unroll
        for (int m = 0; m < MT; m++) a[m] = 0.f;
        for (int j = 0; j < HID_; j++){
            float w = Wk1[(48+j)*HID_ + c];
            FMA16(a, sX + j*20, w);
        }
        #pragma unroll
        for (int m = 0; m < MT; m++) g_ks[(bn0+m)*HID_ + c] = a[m];
    } else {
        int cc = c - HID_;
        float tt = bk1[cc];
        #pragma unroll
        for (int j = 0; j < TD; j++) tt += st[j]*Wk1[(32+j)*HID_ + cc];
        float a[MT];
        #pragma unroll
        for (int m = 0; m < MT; m++) a[m] = tt;
        for (int j = 0; j < HID_; j++){
            float w = Wk1[(176+j)*HID_ + cc];
            FMA16(a, sX + j*20, w);
        }
        #pragma unroll
        for (int m = 0; m < MT; m++) g_kd[(bn0+m)*HID_ + cc] = a[m];
    }

    // qk: warp = head, lane = j (4 iters). sQ reads are warp-broadcast.
    {
        int h = c >> 5, lane = c & 31;
        #pragma unroll
        for (int i = 0; i < 4; i++){
            int j = i*32 + lane;
            const float4* W4 = reinterpret_cast<const float4*>(Wk2 + j*DD + h*DHD);
            float4 w0=W4[0], w1=W4[1], w2=W4[2], w3=W4[3],
                   w4=W4[4], w5=W4[5], w6=W4[6], w7=W4[7];
            #pragma unroll
            for (int m = 0; m < MT; m++){
                const float4* q4 = reinterpret_cast<const float4*>(sQ + m*DD + h*DHD);
                float4 q0=q4[0], q1=q4[1], q2=q4[2], q3=q4[3],
                       q5=q4[4], q6=q4[5], q7=q4[6], q8=q4[7];
                float acc = w0.x*q0.x + w0.y*q0.y + w0.z*q0.z + w0.w*q0.w
                          + w1.x*q1.x + w1.y*q1.y + w1.z*q1.z + w1.w*q1.w
                          + w2.x*q2.x + w2.y*q2.y + w2.z*q2.z + w2.w*q2.w
                          + w3.x*q3.x + w3.y*q3.y + w3.z*q3.z + w3.w*q3.w
                          + w4.x*q5.x + w4.y*q5.y + w4.z*q5.z + w4.w*q5.w
                          + w5.x*q6.x + w5.y*q6.y + w5.z*q6.z + w5.w*q6.w
                          + w6.x*q7.x + w6.y*q7.y + w6.z*q7.z + w6.w*q7.w
                          + w7.x*q8.x + w7.y*q8.y + w7.z*q8.z + w7.w*q8.w;
                g_qk[(bn0+m)*QKW + h*HID_ + j] = acc;
            }
        }
    }
}

// ---------------- attention: one block per (b, node) ----------------
__global__ void __launch_bounds__(256) attn_kernel(
        const float* __restrict__ Wk1,    // W_r rows [0:32)
        const float* __restrict__ WvSh){  // Wv rows [256:265)
    __shared__ float skd[HID_];
    __shared__ float sqkT[NH*132];
    __shared__ float srbfT[NBF*36];   // [j][k], pad 36
    __shared__ float ssh[KK*SHD_];
    __shared__ float scut[KK];
    __shared__ int   ssrc[KK];        // global node index
    __shared__ float sH[KK*132];      // pad 132
    __shared__ float slog[KK*NH];
    __shared__ float salpha[KK*NH];
    __shared__ float smax[NH], ssum[NH];
    __shared__ float shw[NH*SHD_];

    int bn = blockIdx.x, tid = threadIdx.x;
    int b = bn / NN;
    int ebase = bn*KK;

    if (tid < HID_) skd[tid] = g_kd[bn*HID_ + tid];
    if (tid < KK){ ssrc[tid] = b*NN + g_src[ebase + tid]; scut[tid] = g_cut[ebase + tid]; }
    for (int q = tid; q < KK*NBF; q += 256){
        int k = q >> 5, j = q & 31;
        srbfT[j*36 + k] = g_rbf[ebase*NBF + q];
    }
    for (int q = tid; q < KK*SHD_; q += 256) ssh[q] = g_sh[ebase*SHD_ + q];
    for (int q = tid; q < QKW; q += 256){
        int h = q >> 7, j = q & 127;
        sqkT[h*132 + j] = g_qk[bn*QKW + q];
    }
    __syncthreads();

    // h[k,c] = gelu(kd[c] + ks[src_k][c] + rbf[k,:] @ W_r[:,c])
    {
        int c = tid & 127, k0 = tid >> 7;
        float acc[16];
        #pragma unroll
        for (int i = 0; i < 16; i++)
            acc[i] = skd[c] + g_ks[ssrc[k0*16 + i]*HID_ + c];
        for (int j = 0; j < NBF; j++){
            float w = Wk1[j*HID_ + c];
            FMA16(acc, srbfT + j*36 + k0*16, w);
        }
        #pragma unroll
        for (int i = 0; i < 16; i++)
            sH[(k0*16 + i)*132 + c] = gelu_t(acc[i]);
    }
    __syncthreads();

    // logits[k,h]
    {
        int k = tid >> 3, h = tid & 7;
        const float4* h4 = reinterpret_cast<const float4*>(sH + k*132);
        const float4* q4 = reinterpret_cast<const float4*>(sqkT + h*132);
        float acc = 0.f;
        #pragma unroll
        for (int d = 0; d < 32; d++){
            float4 a = h4[d], bq = q4[d];
            acc += a.x*bq.x + a.y*bq.y + a.z*bq.z + a.w*bq.w;
        }
        slog[k*NH + h] = acc*0.17677669529663687f;
    }
    __syncthreads();
    if (tid < NH){
        int h = tid;
        float m = -1e30f;
        for (int k = 0; k < KK; k++) m = fmaxf(m, slog[k*NH + h]);
        float s = 0.f;
        for (int k = 0; k < KK; k++) s += scut[k]*expf(slog[k*NH + h] - m);
        smax[h] = m; ssum[h] = s;
    }
    __syncthreads();
    {
        int k = tid >> 3, h = tid & 7;
        salpha[k*NH + h] = scut[k]*expf(slog[k*NH + h] - smax[h]) / (ssum[h] + 1e-9f);
    }
    __syncthreads();
    if (tid < NH*SHD_){
        int h = tid / SHD_, j = tid % SHD_;
        float s = 0.f;
        for (int k = 0; k < KK; k++) s += salpha[k*NH + h]*ssh[k*SHD_ + j];
        shw[tid] = s;
    }
    __syncthreads();
    {
        int c = tid, h = c >> 5;
        float out = 0.f;
        #pragma unroll
        for (int j = 0; j < SHD_; j++) out += shw[h*SHD_ + j]*WvSh[j*DD + c];
        #pragma unroll 8
        for (int k = 0; k < KK; k++) out += salpha[k*NH + h]*g_vs[ssrc[k]*DD + c];
        g_agg[bn*DD + c] = out;
    }
}

// ---------------- final projection to 3 (warp per output col) ----------------
__global__ void final_kernel(const float* __restrict__ Wo_out, float* __restrict__ out){
    int bn = blockIdx.x, tid = threadIdx.x;
    int w = tid >> 5, lane = tid & 31;   // w in 0..2
    float acc = 0.f;
    for (int j = lane; j < DD; j += 32)
        acc += g_agg[bn*DD + j]*Wo_out[j*3 + w];
    #pragma unroll
    for (int off = 16; off; off >>= 1)
        acc += __shfl_xor_sync(0xFFFFFFFFu, acc, off);
    if (lane == 0) out[bn*3 + w] = acc;
}

extern "C" void kernel_launch(void* const* d_in, const int* in_sizes, int n_in,
                              void* d_out, int out_size){
    const float* x      = (const float*)d_in[0];
    const float* y      = (const float*)d_in[1];
    const float* t      = (const float*)d_in[2];
    const float* We     = (const float*)d_in[3];
    const float* Wk1    = (const float*)d_in[4];
    const float* bk1    = (const float*)d_in[5];
    const float* Wk2    = (const float*)d_in[6];
    const float* Wq     = (const float*)d_in[7];
    const float* Wv     = (const float*)d_in[8];
    const float* Wo     = (const float*)d_in[9];
    const float* Wo_out = (const float*)d_in[10];
    float* out = (float*)d_out;

    knn_kernel<<<dim3(NN, BB), 32>>>(x);
    edge_kernel<<<(BB*NN*KK + 255)/256, 256>>>(x);
    embed_kernel<<<BB*NN, 256>>>(y, t, We);

    for (int l = 0; l < NL; l++){
        const float* Wk1_l = Wk1 + (size_t)l*EIN_*HID_;
        const float* Wv_l  = Wv  + (size_t)l*(DD+SHD_)*DD;
        const float* Wo_prev = (l > 0) ? (Wo + (size_t)(l-1)*DD*DD) : nullptr;
        nodeproj_kernel<<<BB*NN/MT, 256>>>(Wq + (size_t)l*DD*DD, Wk1_l,
                                           bk1 + (size_t)l*HID_,
                                           Wk2 + (size_t)l*HID_*DD,
                                           Wv_l, Wo_prev, t);
        attn_kernel<<<BB*NN, 256>>>(Wk1_l, Wv_l + (size_t)DD*DD);
    }
    final_kernel<<<BB*NN, 96>>>(Wo_out, out);
}

// round 7
// speedup vs baseline: 10.4694x; 1.0026x over previous
#include <cuda_runtime.h>
#include <math.h>

#define BB   8
#define NN   1024
#define KK   32
#define DD   256
#define NH   8
#define DHD  32
#define TD   16
#define NBF  32
#define HID_ 128
#define NS_  128
#define SHD_ 9
#define EIN_ 304
#define NL   4
#define MT   16      // nodes per nodeproj block
#define QKW  (HID_*NH)   // 1024

// ---- scratch (device globals; no allocation allowed) ----
__device__ int   g_src [BB*NN*KK];
__device__ float g_cut [BB*NN*KK];
__device__ float g_sh  [BB*NN*KK*SHD_];
__device__ float g_rbf [BB*NN*KK*NBF];
__device__ float g_node[BB*NN*DD];
__device__ float g_ks  [BB*NN*HID_];
__device__ float g_kd  [BB*NN*HID_];
__device__ float g_vs  [BB*NN*DD];
__device__ float g_qk  [BB*NN*QKW];
__device__ float g_agg [BB*NN*DD];

__device__ __forceinline__ float gelu_t(float x){
    float x3 = x*x*x;
    return 0.5f*x*(1.0f + tanhf(0.7978845608028654f*(x + 0.044715f*x3)));
}

// 16 FFMA fed by 4 broadcast LDS.128 from transposed tile row
#define FMA16(acc, base, w) { \
    const float4* _v4 = reinterpret_cast<const float4*>(base); \
    float4 _a0=_v4[0], _a1=_v4[1], _a2=_v4[2], _a3=_v4[3]; \
    acc[0]+=_a0.x*(w); acc[1]+=_a0.y*(w); acc[2]+=_a0.z*(w); acc[3]+=_a0.w*(w); \
    acc[4]+=_a1.x*(w); acc[5]+=_a1.y*(w); acc[6]+=_a1.z*(w); acc[7]+=_a1.w*(w); \
    acc[8]+=_a2.x*(w); acc[9]+=_a2.y*(w); acc[10]+=_a2.z*(w); acc[11]+=_a2.w*(w); \
    acc[12]+=_a3.x*(w); acc[13]+=_a3.y*(w); acc[14]+=_a3.z*(w); acc[15]+=_a3.w*(w); }

// ---------------- kNN: one warp per node, select 32 smallest (d2,idx) ----------------
__global__ void knn_kernel(const float* __restrict__ x){
    __shared__ unsigned long long keys[NN];
    int b = blockIdx.y, i = blockIdx.x, lane = threadIdx.x;
    const float* pos = x + b*NN*3;
    float xi = pos[3*i], yi = pos[3*i+1], zi = pos[3*i+2];
    for (int j = lane; j < NN; j += 32){
        float dx = xi - pos[3*j], dy = yi - pos[3*j+1], dz = zi - pos[3*j+2];
        float d2 = dx*dx + dy*dy + dz*dz;
        keys[j] = (((unsigned long long)__float_as_uint(d2)) << 32) | (unsigned int)j;
    }
    __syncwarp();
    int base = (b*NN + i)*KK;
    for (int k = 0; k < KK; k++){
        unsigned long long m = 0xFFFFFFFFFFFFFFFFULL; int mp = -1;
        for (int j = lane; j < NN; j += 32)
            if (keys[j] < m){ m = keys[j]; mp = j; }
        unsigned long long gm = m;
        #pragma unroll
        for (int off = 16; off; off >>= 1){
            unsigned long long o = __shfl_xor_sync(0xFFFFFFFFu, gm, off);
            if (o < gm) gm = o;
        }
        if (m == gm && mp >= 0) keys[mp] = 0xFFFFFFFFFFFFFFFFULL;
        if (lane == 0) g_src[base + k] = (int)(gm & 0xFFFFFFFFULL);
        __syncwarp();
    }
}

// ---------------- edge geometry: sh, cut, rbf ----------------
__global__ void edge_kernel(const float* __restrict__ x){
    int e = blockIdx.x*blockDim.x + threadIdx.x;
    if (e >= BB*NN*KK) return;
    int b = e / (NN*KK);
    int i = (e / KK) % NN;
    int s = g_src[e];
    const float* pos = x + b*NN*3;
    float vx = pos[3*i]-pos[3*s], vy = pos[3*i+1]-pos[3*s+1], vz = pos[3*i+2]-pos[3*s+2];
    float r = sqrtf(vx*vx + vy*vy + vz*vz);
    float inv = 1.0f / fmaxf(r, 1e-9f);
    float ux = vx*inv, uy = vy*inv, uz = vz*inv;
    float sh[9];
    sh[0] = 1.0f;
    sh[1] = 1.7320508075688772f*ux;
    sh[2] = 1.7320508075688772f*uy;
    sh[3] = 1.7320508075688772f*uz;
    sh[4] = 3.872983346207417f*ux*uy;
    sh[5] = 3.872983346207417f*uy*uz;
    sh[6] = 1.118033988749895f*(3.0f*uz*uz - 1.0f);
    sh[7] = 3.872983346207417f*ux*uz;
    sh[8] = 1.9364916731037085f*(ux*ux - uy*uy);
    #pragma unroll
    for (int m = 0; m < 9; m++) g_sh[e*9+m] = sh[m];
    float arg = 10.0f*(1.0f - r*0.5f);
    float cut = (arg > 0.0f) ? 1.4f*expf(-1.0f/arg) : 0.0f;
    g_cut[e] = cut;
    const float scale = 4.7982245866f; // sqrt(32)*0.95/1.12
    #pragma unroll
    for (int m = 0; m < NBF; m++){
        float c = 2.0f*(float)m/31.0f;
        float d = (r - c)*15.5f;
        g_rbf[e*NBF+m] = expf(-d*d)*scale*cut;
    }
}

// ---------------- node embedding ----------------
__global__ void embed_kernel(const float* __restrict__ y, const float* __restrict__ t,
                             const float* __restrict__ We){
    int bn = blockIdx.x, c = threadIdx.x;
    int b = bn / NN;
    __shared__ float in[19];
    if (c < 3) in[c] = y[bn*3+c];
    else if (c < 19) in[c] = t[b*TD + c-3];
    __syncthreads();
    float acc = 0.f;
    #pragma unroll
    for (int j = 0; j < 19; j++) acc += in[j]*We[j*DD + c];
    g_node[bn*DD + c] = acc;
}

// ---------------- per-node work, 16 nodes per block ----------------
// (optional fused update) node = act(node + agg @ Wo)
// q  = node @ Wq  (kept in smem only)
// vs = node @ Wv[0:256]
// ks = node[:128] @ Wk1[48:176]
// kd = node[:128] @ Wk1[176:304] + t @ Wk1[32:48] + bk1
// qk[h,j] = sum_{dh} q[h*32+dh] * Wk2[j, h*32+dh]
__global__ void __launch_bounds__(256) nodeproj_kernel(
        const float* __restrict__ Wq,  const float* __restrict__ Wk1,
        const float* __restrict__ bk1, const float* __restrict__ Wk2,
        const float* __restrict__ Wv,  const float* __restrict__ Wo,
        const float* __restrict__ t){
    __shared__ float sX[DD*20];     // transposed tile [j][m], pad 20
    __shared__ float sQ[MT*DD];     // q per node [m][c]
    __shared__ float st[TD];
    int c = threadIdx.x;
    int bn0 = blockIdx.x*MT;
    int b = bn0 / NN;
    if (c < TD) st[c] = t[b*TD + c];

    if (Wo){
        // fused residual update: stage agg transposed, then node = act(node + agg@Wo)
        #pragma unroll
        for (int m = 0; m < MT; m++) sX[c*20 + m] = g_agg[(bn0+m)*DD + c];
        __syncthreads();
        float acc[MT];
        #pragma unroll
        for (int m = 0; m < MT; m++) acc[m] = g_node[(bn0+m)*DD + c];
        for (int j = 0; j < DD; j++){
            float w = Wo[j*DD + c];
            FMA16(acc, sX + j*20, w);
        }
        #pragma unroll
        for (int m = 0; m < MT; m++){
            float v = acc[m];
            if (c < 64)       v = gelu_t(v);
            else if (c < NS_) v = tanhf(v);
            acc[m] = v;
            g_node[(bn0+m)*DD + c] = v;
        }
        __syncthreads();
        #pragma unroll
        for (int m = 0; m < MT; m++) sX[c*20 + m] = acc[m];
    } else {
        #pragma unroll
        for (int m = 0; m < MT; m++) sX[c*20 + m] = g_node[(bn0+m)*DD + c];
    }
    __syncthreads();

    // q + vs
    {
        float aq[MT], av[MT];
        #pragma unroll
        for (int m = 0; m < MT; m++){ aq[m] = 0.f; av[m] = 0.f; }
        for (int j = 0; j < DD; j++){
            float wq = Wq[j*DD + c];
            float wv = Wv[j*DD + c];
            const float4* v4 = reinterpret_cast<const float4*>(sX + j*20);
            float4 a0=v4[0], a1=v4[1], a2=v4[2], a3=v4[3];
            aq[0]+=a0.x*wq; av[0]+=a0.x*wv;  aq[1]+=a0.y*wq; av[1]+=a0.y*wv;
            aq[2]+=a0.z*wq; av[2]+=a0.z*wv;  aq[3]+=a0.w*wq; av[3]+=a0.w*wv;
            aq[4]+=a1.x*wq; av[4]+=a1.x*wv;  aq[5]+=a1.y*wq; av[5]+=a1.y*wv;
            aq[6]+=a1.z*wq; av[6]+=a1.z*wv;  aq[7]+=a1.w*wq; av[7]+=a1.w*wv;
            aq[8]+=a2.x*wq; av[8]+=a2.x*wv;  aq[9]+=a2.y*wq; av[9]+=a2.y*wv;
            aq[10]+=a2.z*wq; av[10]+=a2.z*wv; aq[11]+=a2.w*wq; av[11]+=a2.w*wv;
            aq[12]+=a3.x*wq; av[12]+=a3.x*wv; aq[13]+=a3.y*wq; av[13]+=a3.y*wv;
            aq[14]+=a3.z*wq; av[14]+=a3.z*wv; aq[15]+=a3.w*wq; av[15]+=a3.w*wv;
        }
        #pragma unroll
        for (int m = 0; m < MT; m++){
            g_vs[(bn0+m)*DD + c] = av[m];
            sQ[m*DD + c] = aq[m];
        }
    }
    __syncthreads();

    // ks / kd (split threads)
    if (c < HID_){
        float a[MT];
        #pragma unroll
        for (int m = 0; m < MT; m++) a[m] = 0.f;
        for (int j = 0; j < HID_; j++){
            float w = Wk1[(48+j)*HID_ + c];
            FMA16(a, sX + j*20, w);
        }
        #pragma unroll
        for (int m = 0; m < MT; m++) g_ks[(bn0+m)*HID_ + c] = a[m];
    } else {
        int cc = c - HID_;
        float tt = bk1[cc];
        #pragma unroll
        for (int j = 0; j < TD; j++) tt += st[j]*Wk1[(32+j)*HID_ + cc];
        float a[MT];
        #pragma unroll
        for (int m = 0; m < MT; m++) a[m] = tt;
        for (int j = 0; j < HID_; j++){
            float w = Wk1[(176+j)*HID_ + cc];
            FMA16(a, sX + j*20, w);
        }
        #pragma unroll
        for (int m = 0; m < MT; m++) g_kd[(bn0+m)*HID_ + cc] = a[m];
    }

    // qk: warp = head, lane = j (4 iters). sQ reads are warp-broadcast.
    {
        int h = c >> 5, lane = c & 31;
        #pragma unroll
        for (int i = 0; i < 4; i++){
            int j = i*32 + lane;
            const float4* W4 = reinterpret_cast<const float4*>(Wk2 + j*DD + h*DHD);
            float4 w0=W4[0], w1=W4[1], w2=W4[2], w3=W4[3],
                   w4=W4[4], w5=W4[5], w6=W4[6], w7=W4[7];
            #pragma unroll
            for (int m = 0; m < MT; m++){
                const float4* q4 = reinterpret_cast<const float4*>(sQ + m*DD + h*DHD);
                float4 q0=q4[0], q1=q4[1], q2=q4[2], q3=q4[3],
                       q5=q4[4], q6=q4[5], q7=q4[6], q8=q4[7];
                float acc = w0.x*q0.x + w0.y*q0.y + w0.z*q0.z + w0.w*q0.w
                          + w1.x*q1.x + w1.y*q1.y + w1.z*q1.z + w1.w*q1.w
                          + w2.x*q2.x + w2.y*q2.y + w2.z*q2.z + w2.w*q2.w
                          + w3.x*q3.x + w3.y*q3.y + w3.z*q3.z + w3.w*q3.w
                          + w4.x*q5.x + w4.y*q5.y + w4.z*q5.z + w4.w*q5.w
                          + w5.x*q6.x + w5.y*q6.y + w5.z*q6.z + w5.w*q6.w
                          + w6.x*q7.x + w6.y*q7.y + w6.z*q7.z + w6.w*q7.w
                          + w7.x*q8.x + w7.y*q8.y + w7.z*q8.z + w7.w*q8.w;
                g_qk[(bn0+m)*QKW + h*HID_ + j] = acc;
            }
        }
    }
}

// ---------------- attention: one block per (b, node) ----------------
__global__ void __launch_bounds__(256) attn_kernel(
        const float* __restrict__ Wk1,    // W_r rows [0:32)
        const float* __restrict__ WvSh){  // Wv rows [256:265)
    __shared__ float skd[HID_];
    __shared__ float sqkT[NH*132];
    __shared__ float srbfT[NBF*36];   // [j][k], pad 36
    __shared__ float ssh[KK*SHD_];
    __shared__ float scut[KK];
    __shared__ int   ssrc[KK];        // global node index
    __shared__ float sH[KK*132];      // pad 132
    __shared__ float slog[KK*NH];
    __shared__ float salpha[KK*NH];
    __shared__ float smax[NH], ssum[NH];
    __shared__ float shw[NH*SHD_];

    int bn = blockIdx.x, tid = threadIdx.x;
    int b = bn / NN;
    int ebase = bn*KK;

    if (tid < HID_) skd[tid] = g_kd[bn*HID_ + tid];
    if (tid < KK){ ssrc[tid] = b*NN + g_src[ebase + tid]; scut[tid] = g_cut[ebase + tid]; }
    for (int q = tid; q < KK*NBF; q += 256){
        int k = q >> 5, j = q & 31;
        srbfT[j*36 + k] = g_rbf[ebase*NBF + q];
    }
    for (int q = tid; q < KK*SHD_; q += 256) ssh[q] = g_sh[ebase*SHD_ + q];
    for (int q = tid; q < QKW; q += 256){
        int h = q >> 7, j = q & 127;
        sqkT[h*132 + j] = g_qk[bn*QKW + q];
    }
    __syncthreads();

    // h[k,c] = gelu(kd[c] + ks[src_k][c] + rbf[k,:] @ W_r[:,c])
    {
        int c = tid & 127, k0 = tid >> 7;
        float acc[16];
        #pragma unroll
        for (int i = 0; i < 16; i++)
            acc[i] = skd[c] + g_ks[ssrc[k0*16 + i]*HID_ + c];
        for (int j = 0; j < NBF; j++){
            float w = Wk1[j*HID_ + c];
            FMA16(acc, srbfT + j*36 + k0*16, w);
        }
        #pragma unroll
        for (int i = 0; i < 16; i++)
            sH[(k0*16 + i)*132 + c] = gelu_t(acc[i]);
    }
    __syncthreads();

    // logits[k,h]
    {
        int k = tid >> 3, h = tid & 7;
        const float4* h4 = reinterpret_cast<const float4*>(sH + k*132);
        const float4* q4 = reinterpret_cast<const float4*>(sqkT + h*132);
        float acc = 0.f;
        #pragma unroll
        for (int d = 0; d < 32; d++){
            float4 a = h4[d], bq = q4[d];
            acc += a.x*bq.x + a.y*bq.y + a.z*bq.z + a.w*bq.w;
        }
        slog[k*NH + h] = acc*0.17677669529663687f;
    }
    __syncthreads();
    if (tid < NH){
        int h = tid;
        float m = -1e30f;
        for (int k = 0; k < KK; k++) m = fmaxf(m, slog[k*NH + h]);
        float s = 0.f;
        for (int k = 0; k < KK; k++) s += scut[k]*expf(slog[k*NH + h] - m);
        smax[h] = m; ssum[h] = s;
    }
    __syncthreads();
    {
        int k = tid >> 3, h = tid & 7;
        salpha[k*NH + h] = scut[k]*expf(slog[k*NH + h] - smax[h]) / (ssum[h] + 1e-9f);
    }
    __syncthreads();
    if (tid < NH*SHD_){
        int h = tid / SHD_, j = tid % SHD_;
        float s = 0.f;
        for (int k = 0; k < KK; k++) s += salpha[k*NH + h]*ssh[k*SHD_ + j];
        shw[tid] = s;
    }
    __syncthreads();
    {
        int c = tid, h = c >> 5;
        float out = 0.f;
        #pragma unroll
        for (int j = 0; j < SHD_; j++) out += shw[h*SHD_ + j]*WvSh[j*DD + c];
        #pragma unroll 8
        for (int k = 0; k < KK; k++) out += salpha[k*NH + h]*g_vs[ssrc[k]*DD + c];
        g_agg[bn*DD + c] = out;
    }
}

// ---------------- final projection to 3 (warp per output col) ----------------
__global__ void final_kernel(const float* __restrict__ Wo_out, float* __restrict__ out){
    int bn = blockIdx.x, tid = threadIdx.x;
    int w = tid >> 5, lane = tid & 31;   // w in 0..2
    float acc = 0.f;
    for (int j = lane; j < DD; j += 32)
        acc += g_agg[bn*DD + j]*Wo_out[j*3 + w];
    #pragma unroll
    for (int off = 16; off; off >>= 1)
        acc += __shfl_xor_sync(0xFFFFFFFFu, acc, off);
    if (lane == 0) out[bn*3 + w] = acc;
}

extern "C" void kernel_launch(void* const* d_in, const int* in_sizes, int n_in,
                              void* d_out, int out_size){
    const float* x      = (const float*)d_in[0];
    const float* y      = (const float*)d_in[1];
    const float* t      = (const float*)d_in[2];
    const float* We     = (const float*)d_in[3];
    const float* Wk1    = (const float*)d_in[4];
    const float* bk1    = (const float*)d_in[5];
    const float* Wk2    = (const float*)d_in[6];
    const float* Wq     = (const float*)d_in[7];
    const float* Wv     = (const float*)d_in[8];
    const float* Wo     = (const float*)d_in[9];
    const float* Wo_out = (const float*)d_in[10];
    float* out = (float*)d_out;

    knn_kernel<<<dim3(NN, BB), 32>>>(x);
    edge_kernel<<<(BB*NN*KK + 255)/256, 256>>>(x);
    embed_kernel<<<BB*NN, 256>>>(y, t, We);

    for (int l = 0; l < NL; l++){
        const float* Wk1_l = Wk1 + (size_t)l*EIN_*HID_;
        const float* Wv_l  = Wv  + (size_t)l*(DD+SHD_)*DD;
        const float* Wo_prev = (l > 0) ? (Wo + (size_t)(l-1)*DD*DD) : nullptr;
        nodeproj_kernel<<<BB*NN/MT, 256>>>(Wq + (size_t)l*DD*DD, Wk1_l,
                                           bk1 + (size_t)l*HID_,
                                           Wk2 + (size_t)l*HID_*DD,
                                           Wv_l, Wo_prev, t);
        attn_kernel<<<BB*NN, 256>>>(Wk1_l, Wv_l + (size_t)DD*DD);
    }
    final_kernel<<<BB*NN, 96>>>(Wo_out, out);
}

// round 8
// speedup vs baseline: 12.2183x; 1.1670x over previous
#include <cuda_runtime.h>
#include <math.h>

#define BB   8
#define NN   1024
#define KK   32
#define DD   256
#define NH   8
#define DHD  32
#define TD   16
#define NBF  32
#define HID_ 128
#define NS_  128
#define SHD_ 9
#define EIN_ 304
#define NL   4
#define MT   8       // nodes per nodeproj block
#define QKW  (HID_*NH)   // 1024
#define SXP  12      // sX row stride (8 data + 4 pad, 16B-aligned)

// ---- scratch (device globals; no allocation allowed) ----
__device__ int   g_src [BB*NN*KK];
__device__ float g_cut [BB*NN*KK];
__device__ float g_sh  [BB*NN*KK*SHD_];
__device__ float g_rbf [BB*NN*KK*NBF];
__device__ float g_node[BB*NN*DD];
__device__ float g_ks  [BB*NN*HID_];
__device__ float g_kd  [BB*NN*HID_];
__device__ float g_vs  [BB*NN*DD];
__device__ float g_qk  [BB*NN*QKW];
__device__ float g_agg [BB*NN*DD];
__device__ float g_Wk2T[NL*DD*HID_];   // [l][c][j]

__device__ __forceinline__ float gelu_t(float x){
    float x3 = x*x*x;
    return 0.5f*x*(1.0f + tanhf(0.7978845608028654f*(x + 0.044715f*x3)));
}

// 8 FFMA fed by 2 broadcast LDS.128 from transposed tile row
#define FMA8(acc, base, w) { \
    const float4* _v4 = reinterpret_cast<const float4*>(base); \
    float4 _a0=_v4[0], _a1=_v4[1]; \
    acc[0]+=_a0.x*(w); acc[1]+=_a0.y*(w); acc[2]+=_a0.z*(w); acc[3]+=_a0.w*(w); \
    acc[4]+=_a1.x*(w); acc[5]+=_a1.y*(w); acc[6]+=_a1.z*(w); acc[7]+=_a1.w*(w); }

// ---------------- kNN: one warp per node, select 32 smallest (d2,idx) ----------------
__global__ void knn_kernel(const float* __restrict__ x){
    __shared__ unsigned long long keys[NN];
    int b = blockIdx.y, i = blockIdx.x, lane = threadIdx.x;
    const float* pos = x + b*NN*3;
    float xi = pos[3*i], yi = pos[3*i+1], zi = pos[3*i+2];
    for (int j = lane; j < NN; j += 32){
        float dx = xi - pos[3*j], dy = yi - pos[3*j+1], dz = zi - pos[3*j+2];
        float d2 = dx*dx + dy*dy + dz*dz;
        keys[j] = (((unsigned long long)__float_as_uint(d2)) << 32) | (unsigned int)j;
    }
    __syncwarp();
    int base = (b*NN + i)*KK;
    for (int k = 0; k < KK; k++){
        unsigned long long m = 0xFFFFFFFFFFFFFFFFULL; int mp = -1;
        for (int j = lane; j < NN; j += 32)
            if (keys[j] < m){ m = keys[j]; mp = j; }
        unsigned long long gm = m;
        #pragma unroll
        for (int off = 16; off; off >>= 1){
            unsigned long long o = __shfl_xor_sync(0xFFFFFFFFu, gm, off);
            if (o < gm) gm = o;
        }
        if (m == gm && mp >= 0) keys[mp] = 0xFFFFFFFFFFFFFFFFULL;
        if (lane == 0) g_src[base + k] = (int)(gm & 0xFFFFFFFFULL);
        __syncwarp();
    }
}

// ---------------- edge geometry: sh, cut, rbf ----------------
__global__ void edge_kernel(const float* __restrict__ x){
    int e = blockIdx.x*blockDim.x + threadIdx.x;
    if (e >= BB*NN*KK) return;
    int b = e / (NN*KK);
    int i = (e / KK) % NN;
    int s = g_src[e];
    const float* pos = x + b*NN*3;
    float vx = pos[3*i]-pos[3*s], vy = pos[3*i+1]-pos[3*s+1], vz = pos[3*i+2]-pos[3*s+2];
    float r = sqrtf(vx*vx + vy*vy + vz*vz);
    float inv = 1.0f / fmaxf(r, 1e-9f);
    float ux = vx*inv, uy = vy*inv, uz = vz*inv;
    float sh[9];
    sh[0] = 1.0f;
    sh[1] = 1.7320508075688772f*ux;
    sh[2] = 1.7320508075688772f*uy;
    sh[3] = 1.7320508075688772f*uz;
    sh[4] = 3.872983346207417f*ux*uy;
    sh[5] = 3.872983346207417f*uy*uz;
    sh[6] = 1.118033988749895f*(3.0f*uz*uz - 1.0f);
    sh[7] = 3.872983346207417f*ux*uz;
    sh[8] = 1.9364916731037085f*(ux*ux - uy*uy);
    #pragma unroll
    for (int m = 0; m < 9; m++) g_sh[e*9+m] = sh[m];
    float arg = 10.0f*(1.0f - r*0.5f);
    float cut = (arg > 0.0f) ? 1.4f*expf(-1.0f/arg) : 0.0f;
    g_cut[e] = cut;
    const float scale = 4.7982245866f; // sqrt(32)*0.95/1.12
    #pragma unroll
    for (int m = 0; m < NBF; m++){
        float c = 2.0f*(float)m/31.0f;
        float d = (r - c)*15.5f;
        g_rbf[e*NBF+m] = expf(-d*d)*scale*cut;
    }
}

// ---------------- node embedding ----------------
__global__ void embed_kernel(const float* __restrict__ y, const float* __restrict__ t,
                             const float* __restrict__ We){
    int bn = blockIdx.x, c = threadIdx.x;
    int b = bn / NN;
    __shared__ float in[19];
    if (c < 3) in[c] = y[bn*3+c];
    else if (c < 19) in[c] = t[b*TD + c-3];
    __syncthreads();
    float acc = 0.f;
    #pragma unroll
    for (int j = 0; j < 19; j++) acc += in[j]*We[j*DD + c];
    g_node[bn*DD + c] = acc;
}

// ---------------- Wk2 transpose: [l][j][c] -> [l][c][j] ----------------
__global__ void wk2t_kernel(const float* __restrict__ Wk2){
    int idx = blockIdx.x*256 + threadIdx.x;     // NL*HID_*DD total
    int l = idx / (HID_*DD);
    int r = idx % (HID_*DD);
    int j = r / DD, c = r % DD;
    g_Wk2T[l*DD*HID_ + c*HID_ + j] = Wk2[idx];
}

// ---------------- per-node work, 8 nodes per block ----------------
__global__ void __launch_bounds__(256) nodeproj_kernel(
        const float* __restrict__ Wq,  const float* __restrict__ Wk1,
        const float* __restrict__ bk1, const float* __restrict__ Wk2T,
        const float* __restrict__ Wv,  const float* __restrict__ Wo,
        const float* __restrict__ t){
    __shared__ float sX[DD*SXP];    // transposed tile [j][m]
    __shared__ float sQ[MT*DD];     // q per node [m][c]
    __shared__ float st[TD];
    int c = threadIdx.x;
    int bn0 = blockIdx.x*MT;
    int b = bn0 / NN;
    if (c < TD) st[c] = t[b*TD + c];

    if (Wo){
        // fused residual update: node = act(node + agg @ Wo)
        #pragma unroll
        for (int m = 0; m < MT; m++) sX[c*SXP + m] = g_agg[(bn0+m)*DD + c];
        __syncthreads();
        float acc[MT];
        #pragma unroll
        for (int m = 0; m < MT; m++) acc[m] = g_node[(bn0+m)*DD + c];
        for (int j = 0; j < DD; j++){
            float w = Wo[j*DD + c];
            FMA8(acc, sX + j*SXP, w);
        }
        #pragma unroll
        for (int m = 0; m < MT; m++){
            float v = acc[m];
            if (c < 64)       v = gelu_t(v);
            else if (c < NS_) v = tanhf(v);
            acc[m] = v;
            g_node[(bn0+m)*DD + c] = v;
        }
        __syncthreads();
        #pragma unroll
        for (int m = 0; m < MT; m++) sX[c*SXP + m] = acc[m];
    } else {
        #pragma unroll
        for (int m = 0; m < MT; m++) sX[c*SXP + m] = g_node[(bn0+m)*DD + c];
    }
    __syncthreads();

    // q + vs
    {
        float aq[MT], av[MT];
        #pragma unroll
        for (int m = 0; m < MT; m++){ aq[m] = 0.f; av[m] = 0.f; }
        for (int j = 0; j < DD; j++){
            float wq = Wq[j*DD + c];
            float wv = Wv[j*DD + c];
            const float4* v4 = reinterpret_cast<const float4*>(sX + j*SXP);
            float4 a0 = v4[0], a1 = v4[1];
            aq[0]+=a0.x*wq; av[0]+=a0.x*wv;  aq[1]+=a0.y*wq; av[1]+=a0.y*wv;
            aq[2]+=a0.z*wq; av[2]+=a0.z*wv;  aq[3]+=a0.w*wq; av[3]+=a0.w*wv;
            aq[4]+=a1.x*wq; av[4]+=a1.x*wv;  aq[5]+=a1.y*wq; av[5]+=a1.y*wv;
            aq[6]+=a1.z*wq; av[6]+=a1.z*wv;  aq[7]+=a1.w*wq; av[7]+=a1.w*wv;
        }
        #pragma unroll
        for (int m = 0; m < MT; m++){
            g_vs[(bn0+m)*DD + c] = av[m];
            sQ[m*DD + c] = aq[m];
        }
    }
    __syncthreads();

    // ks / kd (split threads)
    if (c < HID_){
        float a[MT];
        #pragma unroll
        for (int m = 0; m < MT; m++) a[m] = 0.f;
        for (int j = 0; j < HID_; j++){
            float w = Wk1[(48+j)*HID_ + c];
            FMA8(a, sX + j*SXP, w);
        }
        #pragma unroll
        for (int m = 0; m < MT; m++) g_ks[(bn0+m)*HID_ + c] = a[m];
    } else {
        int cc = c - HID_;
        float tt = bk1[cc];
        #pragma unroll
        for (int j = 0; j < TD; j++) tt += st[j]*Wk1[(32+j)*HID_ + cc];
        float a[MT];
        #pragma unroll
        for (int m = 0; m < MT; m++) a[m] = tt;
        for (int j = 0; j < HID_; j++){
            float w = Wk1[(176+j)*HID_ + cc];
            FMA8(a, sX + j*SXP, w);
        }
        #pragma unroll
        for (int m = 0; m < MT; m++) g_kd[(bn0+m)*HID_ + cc] = a[m];
    }

    // qk[m,h,j] = sum_dh sQ[m][h*32+dh] * Wk2T[(h*32+dh)][j]
    // warp = head h, lane = j (4 iterations over j-groups), coalesced W reads.
    {
        int h = c >> 5, lane = c & 31;
        #pragma unroll
        for (int i = 0; i < 4; i++){
            int j = i*32 + lane;
            float acc[MT];
            #pragma unroll
            for (int m = 0; m < MT; m++) acc[m] = 0.f;
            #pragma unroll
            for (int dc = 0; dc < 8; dc++){           // dh chunks of 4
                int dh = dc*4;
                const float* Wp = Wk2T + (h*DHD + dh)*HID_ + j;
                float w0 = Wp[0], w1 = Wp[HID_], w2 = Wp[2*HID_], w3 = Wp[3*HID_];
                #pragma unroll
                for (int m = 0; m < MT; m++){
                    float4 q4 = *reinterpret_cast<const float4*>(sQ + m*DD + h*DHD + dh);
                    acc[m] += q4.x*w0 + q4.y*w1 + q4.z*w2 + q4.w*w3;
                }
            }
            #pragma unroll
            for (int m = 0; m < MT; m++)
                g_qk[(bn0+m)*QKW + h*HID_ + j] = acc[m];
        }
    }
}

// ---------------- attention: one block per (b, node) ----------------
__global__ void __launch_bounds__(256) attn_kernel(
        const float* __restrict__ Wk1,    // W_r rows [0:32)
        const float* __restrict__ WvSh){  // Wv rows [256:265)
    __shared__ float skd[HID_];
    __shared__ float sqkT[NH*132];
    __shared__ float srbfT[NBF*36];   // [j][k], pad 36
    __shared__ float ssh[KK*SHD_];
    __shared__ float scut[KK];
    __shared__ int   ssrc[KK];        // global node index
    __shared__ float sH[KK*132];      // pad 132
    __shared__ float slog[KK*NH];
    __shared__ float salpha[KK*NH];
    __shared__ float smax[NH], ssum[NH];
    __shared__ float shw[NH*SHD_];

    int bn = blockIdx.x, tid = threadIdx.x;
    int b = bn / NN;
    int ebase = bn*KK;

    if (tid < HID_) skd[tid] = g_kd[bn*HID_ + tid];
    if (tid < KK){ ssrc[tid] = b*NN + g_src[ebase + tid]; scut[tid] = g_cut[ebase + tid]; }
    for (int q = tid; q < KK*NBF; q += 256){
        int k = q >> 5, j = q & 31;
        srbfT[j*36 + k] = g_rbf[ebase*NBF + q];
    }
    for (int q = tid; q < KK*SHD_; q += 256) ssh[q] = g_sh[ebase*SHD_ + q];
    for (int q = tid; q < QKW; q += 256){
        int h = q >> 7, j = q & 127;
        sqkT[h*132 + j] = g_qk[bn*QKW + q];
    }
    __syncthreads();

    // h[k,c] = gelu(kd[c] + ks[src_k][c] + rbf[k,:] @ W_r[:,c])
    {
        int c = tid & 127, k0 = tid >> 7;
        float acc[16];
        #pragma unroll
        for (int i = 0; i < 16; i++)
            acc[i] = skd[c] + g_ks[ssrc[k0*16 + i]*HID_ + c];
        for (int j = 0; j < NBF; j++){
            float w = Wk1[j*HID_ + c];
            const float4* v4 = reinterpret_cast<const float4*>(srbfT + j*36 + k0*16);
            float4 a0=v4[0], a1=v4[1], a2=v4[2], a3=v4[3];
            acc[0]+=a0.x*w; acc[1]+=a0.y*w; acc[2]+=a0.z*w; acc[3]+=a0.w*w;
            acc[4]+=a1.x*w; acc[5]+=a1.y*w; acc[6]+=a1.z*w; acc[7]+=a1.w*w;
            acc[8]+=a2.x*w; acc[9]+=a2.y*w; acc[10]+=a2.z*w; acc[11]+=a2.w*w;
            acc[12]+=a3.x*w; acc[13]+=a3.y*w; acc[14]+=a3.z*w; acc[15]+=a3.w*w;
        }
        #pragma unroll
        for (int i = 0; i < 16; i++)
            sH[(k0*16 + i)*132 + c] = gelu_t(acc[i]);
    }
    __syncthreads();

    // logits[k,h]
    {
        int k = tid >> 3, h = tid & 7;
        const float4* h4 = reinterpret_cast<const float4*>(sH + k*132);
        const float4* q4 = reinterpret_cast<const float4*>(sqkT + h*132);
        float acc = 0.f;
        #pragma unroll
        for (int d = 0; d < 32; d++){
            float4 a = h4[d], bq = q4[d];
            acc += a.x*bq.x + a.y*bq.y + a.z*bq.z + a.w*bq.w;
        }
        slog[k*NH + h] = acc*0.17677669529663687f;
    }
    __syncthreads();
    if (tid < NH){
        int h = tid;
        float m = -1e30f;
        for (int k = 0; k < KK; k++) m = fmaxf(m, slog[k*NH + h]);
        float s = 0.f;
        for (int k = 0; k < KK; k++) s += scut[k]*expf(slog[k*NH + h] - m);
        smax[h] = m; ssum[h] = s;
    }
    __syncthreads();
    {
        int k = tid >> 3, h = tid & 7;
        salpha[k*NH + h] = scut[k]*expf(slog[k*NH + h] - smax[h]) / (ssum[h] + 1e-9f);
    }
    __syncthreads();
    if (tid < NH*SHD_){
        int h = tid / SHD_, j = tid % SHD_;
        float s = 0.f;
        for (int k = 0; k < KK; k++) s += salpha[k*NH + h]*ssh[k*SHD_ + j];
        shw[tid] = s;
    }
    __syncthreads();
    {
        int c = tid, h = c >> 5;
        float out = 0.f;
        #pragma unroll
        for (int j = 0; j < SHD_; j++) out += shw[h*SHD_ + j]*WvSh[j*DD + c];
        #pragma unroll 8
        for (int k = 0; k < KK; k++) out += salpha[k*NH + h]*g_vs[ssrc[k]*DD + c];
        g_agg[bn*DD + c] = out;
    }
}

// ---------------- final projection to 3 (warp per output col) ----------------
__global__ void final_kernel(const float* __restrict__ Wo_out, float* __restrict__ out){
    int bn = blockIdx.x, tid = threadIdx.x;
    int w = tid >> 5, lane = tid & 31;   // w in 0..2
    float acc = 0.f;
    for (int j = lane; j < DD; j += 32)
        acc += g_agg[bn*DD + j]*Wo_out[j*3 + w];
    #pragma unroll
    for (int off = 16; off; off >>= 1)
        acc += __shfl_xor_sync(0xFFFFFFFFu, acc, off);
    if (lane == 0) out[bn*3 + w] = acc;
}

extern "C" void kernel_launch(void* const* d_in, const int* in_sizes, int n_in,
                              void* d_out, int out_size){
    const float* x      = (const float*)d_in[0];
    const float* y      = (const float*)d_in[1];
    const float* t      = (const float*)d_in[2];
    const float* We     = (const float*)d_in[3];
    const float* Wk1    = (const float*)d_in[4];
    const float* bk1    = (const float*)d_in[5];
    const float* Wk2    = (const float*)d_in[6];
    const float* Wq     = (const float*)d_in[7];
    const float* Wv     = (const float*)d_in[8];
    const float* Wo     = (const float*)d_in[9];
    const float* Wo_out = (const float*)d_in[10];
    float* out = (float*)d_out;

    knn_kernel<<<dim3(NN, BB), 32>>>(x);
    edge_kernel<<<(BB*NN*KK + 255)/256, 256>>>(x);
    embed_kernel<<<BB*NN, 256>>>(y, t, We);
    wk2t_kernel<<<NL*HID_*DD/256, 256>>>(Wk2);

    float* wk2t_base = nullptr;
    cudaGetSymbolAddress((void**)&wk2t_base, g_Wk2T);

    for (int l = 0; l < NL; l++){
        const float* Wk1_l = Wk1 + (size_t)l*EIN_*HID_;
        const float* Wv_l  = Wv  + (size_t)l*(DD+SHD_)*DD;
        const float* Wo_prev = (l > 0) ? (Wo + (size_t)(l-1)*DD*DD) : nullptr;
        nodeproj_kernel<<<BB*NN/MT, 256>>>(Wq + (size_t)l*DD*DD, Wk1_l,
                                           bk1 + (size_t)l*HID_,
                                           wk2t_base + (size_t)l*DD*HID_,
                                           Wv_l, Wo_prev, t);
        attn_kernel<<<BB*NN, 256>>>(Wk1_l, Wv_l + (size_t)DD*DD);
    }
    final_kernel<<<BB*NN, 96>>>(Wo_out, out);
}